// round 10
// baseline (speedup 1.0000x reference)
#include <cuda_runtime.h>
#include <cuda_fp16.h>
#include <cuda_bf16.h>
#include <cstdint>
#include <cstddef>

// ---------------------------------------------------------------------------
// Problem constants
// ---------------------------------------------------------------------------
#define LEN   13294          // 100*100 + 50*50 + 25*25 + 13*13
#define BATCH 2
#define TOK   (BATCH * LEN)  // 26588
#define NHEAD  8
#define LN_EPS 1e-5f

#define SZ256  ((size_t)TOK * 256)
#define SZ128  ((size_t)TOK * 128)
#define SZ1024 ((size_t)TOK * 1024)

// fp32 buffers: off, attw, x1, ln1, x2. fp16 buffers (in float units /2):
// src_h, query_h, value_h, attnout_h, ln1_h, hid_h. fp16 weights ~754K halves.
#define SCRATCH_FLOATS (4 * SZ256 + SZ128 + (5 * SZ256 + SZ1024) / 2 + 400000)
__device__ float g_scratch[SCRATCH_FLOATS];

// ---------------------------------------------------------------------------
// cp.async helpers
// ---------------------------------------------------------------------------
__device__ __forceinline__ void cp_async16(void* smem, const void* gmem, bool pred) {
    uint32_t s = (uint32_t)__cvta_generic_to_shared(smem);
    int sz = pred ? 16 : 0;
    asm volatile("cp.async.cg.shared.global [%0], [%1], 16, %2;\n"
                 :: "r"(s), "l"(gmem), "r"(sz));
}
__device__ __forceinline__ void cp_commit() {
    asm volatile("cp.async.commit_group;\n" ::);
}
template <int N>
__device__ __forceinline__ void cp_wait() {
    asm volatile("cp.async.wait_group %0;\n" :: "n"(N));
}

#define MMA_F16(d, a, b)                                                      \
    asm volatile(                                                             \
        "mma.sync.aligned.m16n8k16.row.col.f32.f16.f16.f32 "                  \
        "{%0,%1,%2,%3},{%4,%5,%6,%7},{%8,%9},{%0,%1,%2,%3};"                  \
        : "+f"(d[0]), "+f"(d[1]), "+f"(d[2]), "+f"(d[3])                      \
        : "r"(a[0]), "r"(a[1]), "r"(a[2]), "r"(a[3]), "r"(b[0]), "r"(b[1]))

// ---------------------------------------------------------------------------
// Elementwise add + convert: query_h = h(src+pos), src_h = h(src)
// ---------------------------------------------------------------------------
__global__ void add_cvt_kernel(const float* __restrict__ src, const float* __restrict__ pos,
                               __half* __restrict__ query_h, __half* __restrict__ src_h,
                               int n2) {
    int i = blockIdx.x * blockDim.x + threadIdx.x;
    if (i >= n2) return;
    float2 s = ((const float2*)src)[i];
    float2 p = ((const float2*)pos)[i];
    ((__half2*)query_h)[i] = __floats2half2_rn(s.x + p.x, s.y + p.y);
    ((__half2*)src_h)[i]   = __floats2half2_rn(s.x, s.y);
}

// ---------------------------------------------------------------------------
// Weight transpose + convert: out[n*K + k] = half(in[k*N + n])
// ---------------------------------------------------------------------------
__global__ void transpose_cvt_kernel(const float* __restrict__ in, __half* __restrict__ out,
                                     int K, int N) {
    __shared__ float t[32][33];
    int k0 = blockIdx.y * 32, n0 = blockIdx.x * 32;
    int tx = threadIdx.x, ty = threadIdx.y;   // 32 x 8
    #pragma unroll
    for (int i = 0; i < 32; i += 8) {
        int k = k0 + ty + i, n = n0 + tx;
        if (k < K && n < N) t[ty + i][tx] = in[(size_t)k * N + n];
    }
    __syncthreads();
    #pragma unroll
    for (int i = 0; i < 32; i += 8) {
        int n = n0 + ty + i, k = k0 + tx;
        if (n < N && k < K) out[(size_t)n * K + k] = __float2half_rn(t[tx][ty + i]);
    }
}

// ---------------------------------------------------------------------------
// fp16 tensor-core GEMM: C[M,N] = A[M,K] @ Bt^T + bias (+res fp32) (+relu)
// A [M,K] fp16 row-major; Bt [N,K] fp16 row-major (pre-transposed weight).
// Block 128x128, BK=16, 256 threads (8 warps), warp tile 64x32,
// 4-stage cp.async pipeline + fragment double-buffer. fp32 accumulate.
// Smem rows: 8 data u32 (16 halves) + 4 pad -> stride 12 u32, conflict-free
// frag loads: bank(row*12+tg) distinct for g 0..7 x tg 0..3.
// ---------------------------------------------------------------------------
#define RSTRIDE 12                      // u32 per smem row
#define MAT_U32 (128 * RSTRIDE)         // one matrix, one stage
#define STG_U32 (2 * MAT_U32)           // A + B
#define GEMM_SMEM_BYTES (4 * STG_U32 * 4)   // 49,152

__device__ __forceinline__ void ldfa16(uint32_t (&a)[4][4], const uint32_t* asb,
                                       int wm, int g, int tg) {
    #pragma unroll
    for (int mi = 0; mi < 4; ++mi) {
        int base = (wm + mi * 16 + g) * RSTRIDE + tg;
        a[mi][0] = asb[base];
        a[mi][1] = asb[base + 8 * RSTRIDE];
        a[mi][2] = asb[base + 4];
        a[mi][3] = asb[base + 8 * RSTRIDE + 4];
    }
}
__device__ __forceinline__ void ldfb16(uint32_t (&b)[4][2], const uint32_t* bsb,
                                       int wn, int g, int tg) {
    #pragma unroll
    for (int ni = 0; ni < 4; ++ni) {
        int base = (wn + ni * 8 + g) * RSTRIDE + tg;
        b[ni][0] = bsb[base];
        b[ni][1] = bsb[base + 4];
    }
}

template <bool RELU, typename OutT>
__global__ __launch_bounds__(256, 2) void gemm_fp16(
    const __half* __restrict__ A, const __half* __restrict__ Bt,
    const float* __restrict__ bias, const float* __restrict__ res,
    OutT* __restrict__ C, int M, int N, int K)
{
    extern __shared__ uint32_t smu[];

    const int bm = blockIdx.y * 128;
    const int bn = blockIdx.x * 128;
    const int tid = threadIdx.x;
    const int wid = tid >> 5, lane = tid & 31;
    const int wm = (wid & 1) * 64;
    const int wn = (wid >> 1) * 32;
    const int g = lane >> 2, tg = lane & 3;

    // loaders: 2 threads per row, 16B chunk each (8 halves)
    const int lrow = tid >> 1;
    const int lc = tid & 1;
    const uint32_t soff = (uint32_t)lrow * RSTRIDE + (uint32_t)lc * 4;
    const bool aok = (bm + lrow) < M;
    const __half* Ap = A + (size_t)(bm + lrow) * K + lc * 8;
    const __half* Bp = Bt + (size_t)(bn + lrow) * K + lc * 8;

    const int nst = K >> 4;

    // prologue: stages 0..2
    #pragma unroll
    for (int s = 0; s < 3; ++s) {
        uint32_t* ab = smu + (s & 3) * STG_U32;
        uint32_t* bb = ab + MAT_U32;
        cp_async16(ab + soff, Ap + s * 16, aok);
        cp_async16(bb + soff, Bp + s * 16, true);
        cp_commit();
    }

    float acc[4][4][4];
    #pragma unroll
    for (int mi = 0; mi < 4; ++mi)
        #pragma unroll
        for (int ni = 0; ni < 4; ++ni)
            #pragma unroll
            for (int e = 0; e < 4; ++e) acc[mi][ni][e] = 0.f;

    uint32_t fa[2][4][4], fb[2][4][2];

    cp_wait<1>();            // stages <=1 done
    __syncthreads();
    ldfa16(fa[0], smu, wm, g, tg);
    ldfb16(fb[0], smu + MAT_U32, wn, g, tg);

    for (int s = 0; s < nst; ++s) {
        // issue stage s+3 into buf (s+3)&3 = (s-1)&3 (safe: its frags were
        // consumed before the previous iteration's barrier)
        {
            const int sn = s + 3;
            if (sn < nst) {
                uint32_t* ab = smu + (sn & 3) * STG_U32;
                uint32_t* bb = ab + MAT_U32;
                cp_async16(ab + soff, Ap + sn * 16, aok);
                cp_async16(bb + soff, Bp + sn * 16, true);
            }
            cp_commit();
        }

        const int cur = s & 1;
        if (s + 1 < nst) {
            cp_wait<1>();            // stages <= s+2 done
            __syncthreads();
            const uint32_t* an = smu + ((s + 1) & 3) * STG_U32;
            ldfa16(fa[cur ^ 1], an, wm, g, tg);
            ldfb16(fb[cur ^ 1], an + MAT_U32, wn, g, tg);
        }

        #pragma unroll
        for (int mi = 0; mi < 4; ++mi)
            #pragma unroll
            for (int ni = 0; ni < 4; ++ni)
                MMA_F16(acc[mi][ni], fa[cur][mi], fb[cur][ni]);
    }

    // epilogue
    #pragma unroll
    for (int mi = 0; mi < 4; ++mi) {
        int r0 = bm + wm + mi * 16 + g;
        int r1 = r0 + 8;
        #pragma unroll
        for (int ni = 0; ni < 4; ++ni) {
            int col = bn + wn + ni * 8 + 2 * tg;
            float2 bb = *(const float2*)&bias[col];
            #pragma unroll
            for (int half_ = 0; half_ < 2; ++half_) {
                int row = half_ ? r1 : r0;
                if (row >= M) continue;
                float vx = acc[mi][ni][half_ * 2 + 0] + bb.x;
                float vy = acc[mi][ni][half_ * 2 + 1] + bb.y;
                if (res) {
                    float2 rr = *(const float2*)&res[(size_t)row * N + col];
                    vx += rr.x; vy += rr.y;
                }
                if (RELU) { vx = fmaxf(vx, 0.f); vy = fmaxf(vy, 0.f); }
                if constexpr (sizeof(OutT) == 2) {
                    *(__half2*)&C[(size_t)row * N + col] = __floats2half2_rn(vx, vy);
                } else {
                    *(float2*)&C[(size_t)row * N + col] = make_float2(vx, vy);
                }
            }
        }
    }
}

// ---------------------------------------------------------------------------
// Deformable sampling, fused softmax, 2 heads per warp. fp16 out.
// ---------------------------------------------------------------------------
__global__ void sample_kernel(const __half* __restrict__ value,
                              const float* __restrict__ off,
                              const float* __restrict__ logits,
                              const float* __restrict__ ref,
                              __half* __restrict__ out) {
    int gtid = blockIdx.x * blockDim.x + threadIdx.x;
    int gw = gtid >> 5;
    int lane = gtid & 31;
    if (gw >= TOK * 4) return;
    int q = gw >> 2;
    int hp = gw & 3;
    int h = hp * 2 + (lane >> 4);
    int sub = lane & 15;
    int b = q / LEN;

    const int HS[4] = {100, 50, 25, 13};
    const int ST[4] = {0, 10000, 12500, 13125};

    float lg = logits[(size_t)q * 128 + h * 16 + sub];
    float m = lg;
    #pragma unroll
    for (int o = 8; o > 0; o >>= 1) m = fmaxf(m, __shfl_xor_sync(0xffffffffu, m, o));
    float e = __expf(lg - m);
    float ssum = e;
    #pragma unroll
    for (int o = 8; o > 0; o >>= 1) ssum += __shfl_xor_sync(0xffffffffu, ssum, o);
    float wnorm = e / ssum;

    const float* offp = off + (size_t)q * 256 + h * 32;
    const float* refp = ref + (size_t)q * 8;
    const __half2* vb = (const __half2*)(value + (size_t)b * LEN * 256 + h * 32) + sub;

    float accx = 0.f, accy = 0.f;
    #pragma unroll
    for (int l = 0; l < 4; ++l) {
        const int Hl = HS[l];
        const int st = ST[l];
        float rx = refp[l * 2 + 0];
        float ry = refp[l * 2 + 1];
        #pragma unroll
        for (int p = 0; p < 4; ++p) {
            int idx = l * 4 + p;
            float ox = offp[idx * 2 + 0];
            float oy = offp[idx * 2 + 1];
            float w  = __shfl_sync(0xffffffffu, wnorm, (lane & 16) | idx);
            float x = fmaf(rx, (float)Hl, ox - 0.5f);
            float y = fmaf(ry, (float)Hl, oy - 0.5f);
            float x0f = floorf(x), y0f = floorf(y);
            int x0 = (int)x0f, y0 = (int)y0f;
            float dx = x - x0f, dy = y - y0f;

            float mx0 = (x0 >= 0 && x0 < Hl) ? 1.f : 0.f;
            float mx1 = (x0 + 1 >= 0 && x0 + 1 < Hl) ? 1.f : 0.f;
            float my0 = (y0 >= 0 && y0 < Hl) ? 1.f : 0.f;
            float my1 = (y0 + 1 >= 0 && y0 + 1 < Hl) ? 1.f : 0.f;

            int x0c = min(max(x0, 0), Hl - 1);
            int x1c = min(max(x0 + 1, 0), Hl - 1);
            int y0c = min(max(y0, 0), Hl - 1);
            int y1c = min(max(y0 + 1, 0), Hl - 1);

            float w00 = (1.f - dx) * (1.f - dy) * mx0 * my0 * w;
            float w10 = dx * (1.f - dy) * mx1 * my0 * w;
            float w01 = (1.f - dx) * dy * mx0 * my1 * w;
            float w11 = dx * dy * mx1 * my1 * w;

            int r0 = st + y0c * Hl;
            int r1 = st + y1c * Hl;
            float2 v00 = __half22float2(vb[(size_t)(r0 + x0c) * 128]);
            float2 v10 = __half22float2(vb[(size_t)(r0 + x1c) * 128]);
            float2 v01 = __half22float2(vb[(size_t)(r1 + x0c) * 128]);
            float2 v11 = __half22float2(vb[(size_t)(r1 + x1c) * 128]);

            accx += w00 * v00.x + w10 * v10.x + w01 * v01.x + w11 * v11.x;
            accy += w00 * v00.y + w10 * v10.y + w01 * v01.y + w11 * v11.y;
        }
    }
    *(__half2*)&out[(size_t)q * 256 + h * 32 + 2 * sub] = __floats2half2_rn(accx, accy);
}

// ---------------------------------------------------------------------------
// LayerNorm over D=256: one warp per row; optional fp16 twin output
// ---------------------------------------------------------------------------
__global__ void ln_kernel(const float* __restrict__ x, const float* __restrict__ g,
                          const float* __restrict__ be, float* __restrict__ y,
                          __half* __restrict__ yh, int nrows) {
    int gtid = blockIdx.x * blockDim.x + threadIdx.x;
    int row = gtid >> 5;
    int lane = gtid & 31;
    if (row >= nrows) return;
    const float* p = x + (size_t)row * 256 + lane * 8;
    float v[8];
    *(float4*)&v[0] = *(const float4*)(p + 0);
    *(float4*)&v[4] = *(const float4*)(p + 4);
    float s = 0.f;
    #pragma unroll
    for (int i = 0; i < 8; ++i) s += v[i];
    #pragma unroll
    for (int o = 16; o > 0; o >>= 1) s += __shfl_xor_sync(0xffffffffu, s, o);
    float mean = s * (1.f / 256.f);
    float vs = 0.f;
    #pragma unroll
    for (int i = 0; i < 8; ++i) { float d = v[i] - mean; vs += d * d; }
    #pragma unroll
    for (int o = 16; o > 0; o >>= 1) vs += __shfl_xor_sync(0xffffffffu, vs, o);
    float rstd = rsqrtf(vs * (1.f / 256.f) + LN_EPS);
    float* q = y + (size_t)row * 256 + lane * 8;
    const float* gp = g + lane * 8;
    const float* bp = be + lane * 8;
    float go[8], bo[8];
    *(float4*)&go[0] = *(const float4*)(gp + 0);
    *(float4*)&go[4] = *(const float4*)(gp + 4);
    *(float4*)&bo[0] = *(const float4*)(bp + 0);
    *(float4*)&bo[4] = *(const float4*)(bp + 4);
    #pragma unroll
    for (int i = 0; i < 8; ++i) v[i] = (v[i] - mean) * rstd * go[i] + bo[i];
    *(float4*)(q + 0) = *(float4*)&v[0];
    *(float4*)(q + 4) = *(float4*)&v[4];
    if (yh) {
        __half2 h0 = __floats2half2_rn(v[0], v[1]);
        __half2 h1 = __floats2half2_rn(v[2], v[3]);
        __half2 h2 = __floats2half2_rn(v[4], v[5]);
        __half2 h3 = __floats2half2_rn(v[6], v[7]);
        uint4 pk;
        pk.x = *(uint32_t*)&h0; pk.y = *(uint32_t*)&h1;
        pk.z = *(uint32_t*)&h2; pk.w = *(uint32_t*)&h3;
        *(uint4*)&yh[(size_t)row * 256 + lane * 8] = pk;
    }
}

// ---------------------------------------------------------------------------
// Host launch
// ---------------------------------------------------------------------------
extern "C" void kernel_launch(void* const* d_in, const int* in_sizes, int n_in,
                              void* d_out, int out_size) {
    const float* src     = (const float*)d_in[0];
    const float* pos     = (const float*)d_in[1];
    const float* refpts  = (const float*)d_in[2];
    const float* W_value = (const float*)d_in[3];
    const float* b_value = (const float*)d_in[4];
    const float* W_off   = (const float*)d_in[5];
    const float* b_off   = (const float*)d_in[6];
    const float* W_attn  = (const float*)d_in[7];
    const float* b_attn  = (const float*)d_in[8];
    const float* W_out   = (const float*)d_in[9];
    const float* b_out   = (const float*)d_in[10];
    const float* W1      = (const float*)d_in[11];
    const float* b1      = (const float*)d_in[12];
    const float* W2      = (const float*)d_in[13];
    const float* b2      = (const float*)d_in[14];
    const float* g1      = (const float*)d_in[15];
    const float* be1     = (const float*)d_in[16];
    const float* g2      = (const float*)d_in[17];
    const float* be2     = (const float*)d_in[18];
    float* out = (float*)d_out;

    void* sp = nullptr;
    cudaGetSymbolAddress(&sp, g_scratch);
    float* base      = (float*)sp;
    float* g_off     = base;                          // fp32 [M,256]
    float* g_attw    = g_off   + SZ256;               // fp32 [M,128]
    float* g_x1      = g_attw  + SZ128;               // fp32 [M,256]
    float* g_ln1     = g_x1    + SZ256;               // fp32 [M,256]
    float* g_x2      = g_ln1   + SZ256;               // fp32 [M,256]
    float* hbase     = g_x2    + SZ256;
    __half* g_srch    = (__half*)hbase;               // [M,256]
    __half* g_queryh  = g_srch    + SZ256;
    __half* g_valueh  = g_queryh  + SZ256;
    __half* g_attnoh  = g_valueh  + SZ256;
    __half* g_ln1h    = g_attnoh  + SZ256;
    __half* g_hidh    = g_ln1h    + SZ256;            // [M,1024]
    __half* g_wvT     = g_hidh    + SZ1024;           // [256,256]
    __half* g_woffT   = g_wvT     + 256 * 256;
    __half* g_wattnT  = g_woffT   + 256 * 256;        // [128,256]
    __half* g_woutT   = g_wattnT  + 128 * 256;
    __half* g_w1T     = g_woutT   + 256 * 256;        // [1024,256]
    __half* g_w2T     = g_w1T     + 1024 * 256;       // [256,1024]

    cudaFuncSetAttribute(gemm_fp16<false, float>,
                         cudaFuncAttributeMaxDynamicSharedMemorySize, GEMM_SMEM_BYTES);
    cudaFuncSetAttribute(gemm_fp16<false, __half>,
                         cudaFuncAttributeMaxDynamicSharedMemorySize, GEMM_SMEM_BYTES);
    cudaFuncSetAttribute(gemm_fp16<true, __half>,
                         cudaFuncAttributeMaxDynamicSharedMemorySize, GEMM_SMEM_BYTES);

    const int M = TOK;
    const int gy = (M + 127) / 128;   // 208
    dim3 tb(32, 8);

    // 0) weights -> fp16 [N,K]
    transpose_cvt_kernel<<<dim3(8, 8),  tb>>>(W_value, g_wvT,   256, 256);
    transpose_cvt_kernel<<<dim3(8, 8),  tb>>>(W_off,   g_woffT, 256, 256);
    transpose_cvt_kernel<<<dim3(4, 8),  tb>>>(W_attn,  g_wattnT,256, 128);
    transpose_cvt_kernel<<<dim3(8, 8),  tb>>>(W_out,   g_woutT, 256, 256);
    transpose_cvt_kernel<<<dim3(32, 8), tb>>>(W1,      g_w1T,   256, 1024);
    transpose_cvt_kernel<<<dim3(8, 32), tb>>>(W2,      g_w2T,   1024, 256);

    // 1) query_h = h(src+pos); src_h = h(src)
    {
        int n2 = (int)(SZ256 / 2);
        add_cvt_kernel<<<(n2 + 255) / 256, 256>>>(src, pos, g_queryh, g_srch, n2);
    }
    // 2) value = src @ Wv + bv -> fp16
    gemm_fp16<false, __half><<<dim3(2, gy), 256, GEMM_SMEM_BYTES>>>(g_srch, g_wvT, b_value, nullptr, g_valueh, M, 256, 256);
    // 3) off = query @ Woff + boff (fp32 for sampler)
    gemm_fp16<false, float><<<dim3(2, gy), 256, GEMM_SMEM_BYTES>>>(g_queryh, g_woffT, b_off, nullptr, g_off, M, 256, 256);
    // 4) attw logits (fp32)
    gemm_fp16<false, float><<<dim3(1, gy), 256, GEMM_SMEM_BYTES>>>(g_queryh, g_wattnT, b_attn, nullptr, g_attw, M, 128, 256);
    // 5) sampling (+softmax) -> fp16
    {
        int nthreads = TOK * 4 * 32;
        sample_kernel<<<(nthreads + 255) / 256, 256>>>(g_valueh, g_off, g_attw, refpts, g_attnoh);
    }
    // 6) x1 = attnout @ Wout + bout + src (fp32)
    gemm_fp16<false, float><<<dim3(2, gy), 256, GEMM_SMEM_BYTES>>>(g_attnoh, g_woutT, b_out, src, g_x1, M, 256, 256);
    // 7) ln1 -> fp32 + fp16 twin
    {
        int nthreads = TOK * 32;
        ln_kernel<<<(nthreads + 255) / 256, 256>>>(g_x1, g1, be1, g_ln1, g_ln1h, TOK);
    }
    // 8) hid = relu(ln1 @ W1 + b1) -> fp16
    gemm_fp16<true, __half><<<dim3(8, gy), 256, GEMM_SMEM_BYTES>>>(g_ln1h, g_w1T, b1, nullptr, g_hidh, M, 1024, 256);
    // 9) x2 = hid @ W2 + b2 + ln1 (fp32, K=1024)
    gemm_fp16<false, float><<<dim3(2, gy), 256, GEMM_SMEM_BYTES>>>(g_hidh, g_w2T, b2, g_ln1, g_x2, M, 256, 1024);
    // 10) out = LN(x2)
    {
        int nthreads = TOK * 32;
        ln_kernel<<<(nthreads + 255) / 256, 256>>>(g_x2, g2, be2, out, nullptr, TOK);
    }
}

// round 11
// speedup vs baseline: 1.1736x; 1.1736x over previous
#include <cuda_runtime.h>
#include <cuda_fp16.h>
#include <cuda_bf16.h>
#include <cstdint>
#include <cstddef>

// ---------------------------------------------------------------------------
// Problem constants
// ---------------------------------------------------------------------------
#define LEN   13294          // 100*100 + 50*50 + 25*25 + 13*13
#define BATCH 2
#define TOK   (BATCH * LEN)  // 26588
#define NHEAD  8
#define LN_EPS 1e-5f

#define SZ256  ((size_t)TOK * 256)
#define SZ128  ((size_t)TOK * 128)
#define SZ1024 ((size_t)TOK * 1024)

__device__ float g_scratch[7 * SZ256 + SZ128 + SZ1024];

// ---------------------------------------------------------------------------
// Elementwise add
// ---------------------------------------------------------------------------
__global__ void add_kernel(const float* __restrict__ a, const float* __restrict__ b,
                           float* __restrict__ c, int n4) {
    int i = blockIdx.x * blockDim.x + threadIdx.x;
    if (i >= n4) return;
    float4 va = ((const float4*)a)[i];
    float4 vb = ((const float4*)b)[i];
    ((float4*)c)[i] = make_float4(va.x + vb.x, va.y + vb.y, va.z + vb.z, va.w + vb.w);
}

// ---------------------------------------------------------------------------
// cp.async helpers
// ---------------------------------------------------------------------------
__device__ __forceinline__ void cp_async16(void* smem, const void* gmem, bool pred) {
    uint32_t s = (uint32_t)__cvta_generic_to_shared(smem);
    int sz = pred ? 16 : 0;
    asm volatile("cp.async.cg.shared.global [%0], [%1], 16, %2;\n"
                 :: "r"(s), "l"(gmem), "r"(sz));
}
__device__ __forceinline__ void cp_commit() {
    asm volatile("cp.async.commit_group;\n" ::);
}
template <int N>
__device__ __forceinline__ void cp_wait() {
    asm volatile("cp.async.wait_group %0;\n" :: "n"(N));
}

#define MMA_TF32(d, a, b)                                                     \
    asm volatile(                                                             \
        "mma.sync.aligned.m16n8k8.row.col.f32.tf32.tf32.f32 "                 \
        "{%0,%1,%2,%3},{%4,%5,%6,%7},{%8,%9},{%0,%1,%2,%3};"                  \
        : "+f"(d[0]), "+f"(d[1]), "+f"(d[2]), "+f"(d[3])                      \
        : "r"(a[0]), "r"(a[1]), "r"(a[2]), "r"(a[3]), "r"(b[0]), "r"(b[1]))

// ---------------------------------------------------------------------------
// TF32 tensor-core GEMM, BK=32 stages, 3-stage cp.async pipeline + fragment
// double-buffer. Block 128x128, 256 threads (8 warps), warp tile 64x32.
// One cp_wait + barrier per 32-K iteration (half of R7's sync count).
// ---------------------------------------------------------------------------
#define ASTRIDE 36              // 32 + 4 pad (u32 per A row)
#define BSTRIDE 136             // 128 + 8 pad (u32 per B row)
#define A_ELEMS (128 * ASTRIDE) // 4608 u32 per stage
#define B_ELEMS (32 * BSTRIDE)  // 4352 u32 per stage
#define STG_U32 (A_ELEMS + B_ELEMS)
#define NSTAGE 3
#define GEMM_SMEM_BYTES (NSTAGE * STG_U32 * 4)    // 107,520

__device__ __forceinline__ int inc3(int x) { return (x == 2) ? 0 : (x + 1); }

__device__ __forceinline__ void load_frag_a(uint32_t (&a)[4][4], const uint32_t* asb,
                                            int wm, int g, int tg, int kk) {
    #pragma unroll
    for (int mi = 0; mi < 4; ++mi) {
        int base = (wm + mi * 16 + g) * ASTRIDE + kk + tg;
        a[mi][0] = asb[base];
        a[mi][1] = asb[base + 8 * ASTRIDE];
        a[mi][2] = asb[base + 4];
        a[mi][3] = asb[base + 8 * ASTRIDE + 4];
    }
}
__device__ __forceinline__ void load_frag_b(uint32_t (&b)[4][2], const uint32_t* bsb,
                                            int wn, int g, int tg, int kk) {
    #pragma unroll
    for (int ni = 0; ni < 4; ++ni) {
        int c = wn + ni * 8 + g;
        b[ni][0] = bsb[(kk + tg) * BSTRIDE + c];
        b[ni][1] = bsb[(kk + tg + 4) * BSTRIDE + c];
    }
}

template <bool RELU, typename OutT>
__global__ __launch_bounds__(256, 2) void gemm_tc(
    const float* __restrict__ A, const float* __restrict__ W,
    const float* __restrict__ bias, const float* __restrict__ res,
    OutT* __restrict__ C, int M, int N, int K)
{
    extern __shared__ uint32_t smu[];

    const int bm = blockIdx.y * 128;
    const int bn = blockIdx.x * 128;
    const int tid = threadIdx.x;
    const int wid = tid >> 5, lane = tid & 31;
    const int wm = (wid & 1) * 64;
    const int wn = (wid >> 1) * 32;
    const int g = lane >> 2, tg = lane & 3;

    // loaders: A 2 thr/row x 16 floats; B 8 thr/row x 16 floats
    const int arow = tid >> 1;
    const int acol = (tid & 1) * 16;
    const int brow = tid >> 3;            // 0..31 (k index within stage)
    const int bcol = (tid & 7) * 16;      // 0..112
    const bool aok = (bm + arow) < M;
    const float* Ap = A + (size_t)(bm + arow) * K + acol;
    const float* Bp = W + (size_t)brow * N + bn + bcol;

    const int nst = K >> 5;

    // prologue: stages 0,1
    #pragma unroll
    for (int s = 0; s < 2; ++s) {
        uint32_t* ab = smu + s * STG_U32;
        uint32_t* bb = ab + A_ELEMS;
        const int k0 = s << 5;
        #pragma unroll
        for (int c = 0; c < 4; ++c)
            cp_async16(ab + arow * ASTRIDE + acol + 4 * c, Ap + k0 + 4 * c, aok);
        const float* bp = Bp + (size_t)k0 * N;
        #pragma unroll
        for (int c = 0; c < 4; ++c)
            cp_async16(bb + brow * BSTRIDE + bcol + 4 * c, bp + 4 * c, true);
        cp_commit();
    }

    float acc[4][4][4];
    #pragma unroll
    for (int mi = 0; mi < 4; ++mi)
        #pragma unroll
        for (int ni = 0; ni < 4; ++ni)
            #pragma unroll
            for (int e = 0; e < 4; ++e) acc[mi][ni][e] = 0.f;

    uint32_t fa[2][4][4], fb[2][4][2];

    cp_wait<1>();               // stage 0 resident
    __syncthreads();
    load_frag_a(fa[0], smu, wm, g, tg, 0);
    load_frag_b(fb[0], smu + A_ELEMS, wn, g, tg, 0);

    int cbuf = 0;               // buffer of stage s
    int ibuf = 2;               // buffer for stage s+2

    for (int s = 0; s < nst; ++s) {
        // issue stage s+2 into ibuf (held stage s-1; its last frag reads
        // preceded the previous iteration's barrier)
        if (s + 2 < nst) {
            uint32_t* ab = smu + ibuf * STG_U32;
            uint32_t* bb = ab + A_ELEMS;
            const int k0 = (s + 2) << 5;
            #pragma unroll
            for (int c = 0; c < 4; ++c)
                cp_async16(ab + arow * ASTRIDE + acol + 4 * c, Ap + k0 + 4 * c, aok);
            const float* bp = Bp + (size_t)k0 * N;
            #pragma unroll
            for (int c = 0; c < 4; ++c)
                cp_async16(bb + brow * BSTRIDE + bcol + 4 * c, bp + 4 * c, true);
        }
        cp_commit();            // uniform accounting
        ibuf = inc3(ibuf);

        const uint32_t* asb = smu + cbuf * STG_U32;
        const uint32_t* bsb = asb + A_ELEMS;

        // kk = 0 compute, prefetch kk = 8
        load_frag_a(fa[1], asb, wm, g, tg, 8);
        load_frag_b(fb[1], bsb, wn, g, tg, 8);
        #pragma unroll
        for (int mi = 0; mi < 4; ++mi)
            #pragma unroll
            for (int ni = 0; ni < 4; ++ni)
                MMA_TF32(acc[mi][ni], fa[0][mi], fb[0][ni]);

        // kk = 8 compute, prefetch kk = 16
        load_frag_a(fa[0], asb, wm, g, tg, 16);
        load_frag_b(fb[0], bsb, wn, g, tg, 16);
        #pragma unroll
        for (int mi = 0; mi < 4; ++mi)
            #pragma unroll
            for (int ni = 0; ni < 4; ++ni)
                MMA_TF32(acc[mi][ni], fa[1][mi], fb[1][ni]);

        // kk = 16 compute, prefetch kk = 24
        load_frag_a(fa[1], asb, wm, g, tg, 24);
        load_frag_b(fb[1], bsb, wn, g, tg, 24);
        #pragma unroll
        for (int mi = 0; mi < 4; ++mi)
            #pragma unroll
            for (int ni = 0; ni < 4; ++ni)
                MMA_TF32(acc[mi][ni], fa[0][mi], fb[0][ni]);

        // stage s+1 visibility, then prefetch its kk=0 under the last burst
        const int nbuf = inc3(cbuf);
        if (s + 1 < nst) {
            cp_wait<1>();       // stages <= s+1 done (s+2 may be pending)
            __syncthreads();
            const uint32_t* an = smu + nbuf * STG_U32;
            load_frag_a(fa[0], an, wm, g, tg, 0);
            load_frag_b(fb[0], an + A_ELEMS, wn, g, tg, 0);
        }

        // kk = 24 compute
        #pragma unroll
        for (int mi = 0; mi < 4; ++mi)
            #pragma unroll
            for (int ni = 0; ni < 4; ++ni)
                MMA_TF32(acc[mi][ni], fa[1][mi], fb[1][ni]);

        cbuf = nbuf;
    }

    // epilogue
    #pragma unroll
    for (int mi = 0; mi < 4; ++mi) {
        int r0 = bm + wm + mi * 16 + g;
        int r1 = r0 + 8;
        #pragma unroll
        for (int ni = 0; ni < 4; ++ni) {
            int col = bn + wn + ni * 8 + 2 * tg;
            float2 bb = *(const float2*)&bias[col];
            #pragma unroll
            for (int half_ = 0; half_ < 2; ++half_) {
                int row = half_ ? r1 : r0;
                if (row >= M) continue;
                float vx = acc[mi][ni][half_ * 2 + 0] + bb.x;
                float vy = acc[mi][ni][half_ * 2 + 1] + bb.y;
                if (res) {
                    float2 rr = *(const float2*)&res[(size_t)row * N + col];
                    vx += rr.x; vy += rr.y;
                }
                if (RELU) { vx = fmaxf(vx, 0.f); vy = fmaxf(vy, 0.f); }
                if constexpr (sizeof(OutT) == 2) {
                    *(__half2*)&C[(size_t)row * N + col] = __floats2half2_rn(vx, vy);
                } else {
                    *(float2*)&C[(size_t)row * N + col] = make_float2(vx, vy);
                }
            }
        }
    }
}

// ---------------------------------------------------------------------------
// Deformable sampling, fused softmax, 2 heads per warp (unchanged from R7)
// ---------------------------------------------------------------------------
__global__ void sample_kernel(const __half* __restrict__ value,
                              const float* __restrict__ off,
                              const float* __restrict__ logits,
                              const float* __restrict__ ref,
                              float* __restrict__ out) {
    int gtid = blockIdx.x * blockDim.x + threadIdx.x;
    int gw = gtid >> 5;
    int lane = gtid & 31;
    if (gw >= TOK * 4) return;
    int q = gw >> 2;
    int hp = gw & 3;
    int h = hp * 2 + (lane >> 4);
    int sub = lane & 15;
    int b = q / LEN;

    const int HS[4] = {100, 50, 25, 13};
    const int ST[4] = {0, 10000, 12500, 13125};

    float lg = logits[(size_t)q * 128 + h * 16 + sub];
    float m = lg;
    #pragma unroll
    for (int o = 8; o > 0; o >>= 1) m = fmaxf(m, __shfl_xor_sync(0xffffffffu, m, o));
    float e = __expf(lg - m);
    float ssum = e;
    #pragma unroll
    for (int o = 8; o > 0; o >>= 1) ssum += __shfl_xor_sync(0xffffffffu, ssum, o);
    float wnorm = e / ssum;

    const float* offp = off + (size_t)q * 256 + h * 32;
    const float* refp = ref + (size_t)q * 8;
    const __half2* vb = (const __half2*)(value + (size_t)b * LEN * 256 + h * 32) + sub;

    float accx = 0.f, accy = 0.f;
    #pragma unroll
    for (int l = 0; l < 4; ++l) {
        const int Hl = HS[l];
        const int st = ST[l];
        float rx = refp[l * 2 + 0];
        float ry = refp[l * 2 + 1];
        #pragma unroll
        for (int p = 0; p < 4; ++p) {
            int idx = l * 4 + p;
            float ox = offp[idx * 2 + 0];
            float oy = offp[idx * 2 + 1];
            float w  = __shfl_sync(0xffffffffu, wnorm, (lane & 16) | idx);
            float x = fmaf(rx, (float)Hl, ox - 0.5f);
            float y = fmaf(ry, (float)Hl, oy - 0.5f);
            float x0f = floorf(x), y0f = floorf(y);
            int x0 = (int)x0f, y0 = (int)y0f;
            float dx = x - x0f, dy = y - y0f;

            float mx0 = (x0 >= 0 && x0 < Hl) ? 1.f : 0.f;
            float mx1 = (x0 + 1 >= 0 && x0 + 1 < Hl) ? 1.f : 0.f;
            float my0 = (y0 >= 0 && y0 < Hl) ? 1.f : 0.f;
            float my1 = (y0 + 1 >= 0 && y0 + 1 < Hl) ? 1.f : 0.f;

            int x0c = min(max(x0, 0), Hl - 1);
            int x1c = min(max(x0 + 1, 0), Hl - 1);
            int y0c = min(max(y0, 0), Hl - 1);
            int y1c = min(max(y0 + 1, 0), Hl - 1);

            float w00 = (1.f - dx) * (1.f - dy) * mx0 * my0 * w;
            float w10 = dx * (1.f - dy) * mx1 * my0 * w;
            float w01 = (1.f - dx) * dy * mx0 * my1 * w;
            float w11 = dx * dy * mx1 * my1 * w;

            int r0 = st + y0c * Hl;
            int r1 = st + y1c * Hl;
            float2 v00 = __half22float2(vb[(size_t)(r0 + x0c) * 128]);
            float2 v10 = __half22float2(vb[(size_t)(r0 + x1c) * 128]);
            float2 v01 = __half22float2(vb[(size_t)(r1 + x0c) * 128]);
            float2 v11 = __half22float2(vb[(size_t)(r1 + x1c) * 128]);

            accx += w00 * v00.x + w10 * v10.x + w01 * v01.x + w11 * v11.x;
            accy += w00 * v00.y + w10 * v10.y + w01 * v01.y + w11 * v11.y;
        }
    }
    *(float2*)&out[(size_t)q * 256 + h * 32 + 2 * sub] = make_float2(accx, accy);
}

// ---------------------------------------------------------------------------
// LayerNorm over D=256: one warp per row (unchanged from R7)
// ---------------------------------------------------------------------------
__global__ void ln_kernel(const float* __restrict__ x, const float* __restrict__ g,
                          const float* __restrict__ be, float* __restrict__ y,
                          int nrows) {
    int gtid = blockIdx.x * blockDim.x + threadIdx.x;
    int row = gtid >> 5;
    int lane = gtid & 31;
    if (row >= nrows) return;
    const float* p = x + (size_t)row * 256 + lane * 8;
    float v[8];
    *(float4*)&v[0] = *(const float4*)(p + 0);
    *(float4*)&v[4] = *(const float4*)(p + 4);
    float s = 0.f;
    #pragma unroll
    for (int i = 0; i < 8; ++i) s += v[i];
    #pragma unroll
    for (int o = 16; o > 0; o >>= 1) s += __shfl_xor_sync(0xffffffffu, s, o);
    float mean = s * (1.f / 256.f);
    float vs = 0.f;
    #pragma unroll
    for (int i = 0; i < 8; ++i) { float d = v[i] - mean; vs += d * d; }
    #pragma unroll
    for (int o = 16; o > 0; o >>= 1) vs += __shfl_xor_sync(0xffffffffu, vs, o);
    float rstd = rsqrtf(vs * (1.f / 256.f) + LN_EPS);
    float* q = y + (size_t)row * 256 + lane * 8;
    const float* gp = g + lane * 8;
    const float* bp = be + lane * 8;
    float go[8], bo[8];
    *(float4*)&go[0] = *(const float4*)(gp + 0);
    *(float4*)&go[4] = *(const float4*)(gp + 4);
    *(float4*)&bo[0] = *(const float4*)(bp + 0);
    *(float4*)&bo[4] = *(const float4*)(bp + 4);
    #pragma unroll
    for (int i = 0; i < 8; ++i) v[i] = (v[i] - mean) * rstd * go[i] + bo[i];
    *(float4*)(q + 0) = *(float4*)&v[0];
    *(float4*)(q + 4) = *(float4*)&v[4];
}

// ---------------------------------------------------------------------------
// Host launch
// ---------------------------------------------------------------------------
extern "C" void kernel_launch(void* const* d_in, const int* in_sizes, int n_in,
                              void* d_out, int out_size) {
    const float* src     = (const float*)d_in[0];
    const float* pos     = (const float*)d_in[1];
    const float* refpts  = (const float*)d_in[2];
    const float* W_value = (const float*)d_in[3];
    const float* b_value = (const float*)d_in[4];
    const float* W_off   = (const float*)d_in[5];
    const float* b_off   = (const float*)d_in[6];
    const float* W_attn  = (const float*)d_in[7];
    const float* b_attn  = (const float*)d_in[8];
    const float* W_out   = (const float*)d_in[9];
    const float* b_out   = (const float*)d_in[10];
    const float* W1      = (const float*)d_in[11];
    const float* b1      = (const float*)d_in[12];
    const float* W2      = (const float*)d_in[13];
    const float* b2      = (const float*)d_in[14];
    const float* g1      = (const float*)d_in[15];
    const float* be1     = (const float*)d_in[16];
    const float* g2      = (const float*)d_in[17];
    const float* be2     = (const float*)d_in[18];
    float* out = (float*)d_out;

    void* sp = nullptr;
    cudaGetSymbolAddress(&sp, g_scratch);
    float* base      = (float*)sp;
    float* g_query   = base;
    float* g_valuef  = g_query   + SZ256;
    float* g_off     = g_valuef  + SZ256;
    float* g_attnout = g_off     + SZ256;
    float* g_x1      = g_attnout + SZ256;
    float* g_ln1     = g_x1      + SZ256;
    float* g_x2      = g_ln1     + SZ256;
    float* g_attw    = g_x2      + SZ256;
    float* g_hid     = g_attw    + SZ128;
    __half* g_value_h = (__half*)g_valuef;

    cudaFuncSetAttribute(gemm_tc<false, float>,
                         cudaFuncAttributeMaxDynamicSharedMemorySize, GEMM_SMEM_BYTES);
    cudaFuncSetAttribute(gemm_tc<true, float>,
                         cudaFuncAttributeMaxDynamicSharedMemorySize, GEMM_SMEM_BYTES);
    cudaFuncSetAttribute(gemm_tc<false, __half>,
                         cudaFuncAttributeMaxDynamicSharedMemorySize, GEMM_SMEM_BYTES);

    const int M = TOK;
    const int gy = (M + 127) / 128;   // 208

    // 1) query = src + pos
    {
        int n4 = (int)(SZ256 / 4);
        add_kernel<<<(n4 + 255) / 256, 256>>>(src, pos, g_query, n4);
    }
    // 2) value = src @ Wv + bv  -> fp16
    gemm_tc<false, __half><<<dim3(2, gy), 256, GEMM_SMEM_BYTES>>>(src, W_value, b_value, nullptr, g_value_h, M, 256, 256);
    // 3) off = query @ Woff + boff
    gemm_tc<false, float><<<dim3(2, gy), 256, GEMM_SMEM_BYTES>>>(g_query, W_off, b_off, nullptr, g_off, M, 256, 256);
    // 4) attw logits
    gemm_tc<false, float><<<dim3(1, gy), 256, GEMM_SMEM_BYTES>>>(g_query, W_attn, b_attn, nullptr, g_attw, M, 128, 256);
    // 5) sampling (+softmax)
    {
        int nthreads = TOK * 4 * 32;
        sample_kernel<<<(nthreads + 255) / 256, 256>>>(g_value_h, g_off, g_attw, refpts, g_attnout);
    }
    // 6) x1 = attnout @ Wout + bout + src
    gemm_tc<false, float><<<dim3(2, gy), 256, GEMM_SMEM_BYTES>>>(g_attnout, W_out, b_out, src, g_x1, M, 256, 256);
    // 7) ln1
    {
        int nthreads = TOK * 32;
        ln_kernel<<<(nthreads + 255) / 256, 256>>>(g_x1, g1, be1, g_ln1, TOK);
    }
    // 8) hid = relu(ln1 @ W1 + b1)
    gemm_tc<true, float><<<dim3(8, gy), 256, GEMM_SMEM_BYTES>>>(g_ln1, W1, b1, nullptr, g_hid, M, 1024, 256);
    // 9) x2 = hid @ W2 + b2 + ln1
    gemm_tc<false, float><<<dim3(2, gy), 256, GEMM_SMEM_BYTES>>>(g_hid, W2, b2, g_ln1, g_x2, M, 256, 1024);
    // 10) out = LN(x2)
    {
        int nthreads = TOK * 32;
        ln_kernel<<<(nthreads + 255) / 256, 256>>>(g_x2, g2, be2, out, TOK);
    }
}